// round 1
// baseline (speedup 1.0000x reference)
#include <cuda_runtime.h>
#include <math.h>

#define H 1024
#define W 1024
#define TILE 32
#define SG 40   // TILE + 2*4 (gray halo)
#define SB 36   // TILE + 2*2 (blurred halo)
#define SMG 34  // TILE + 2*1 (magnitude halo)
#define NTHREADS 256

__device__ int g_count;

__constant__ int c_dr[8] = {0,-1,-1,-1, 0, 1, 1, 1};
__constant__ int c_dc[8] = {1, 1, 0,-1,-1,-1, 0, 1};

struct Smem {
    float sg[SG][SG];   // gray (reflect-extended)
    float hb[SG][SB];   // horizontal blur (raw rows, clamped cols)
    float sb[SB][SB];   // blurred at (clampY, clampX)
    float sm[SMG][SMG]; // magnitude (0 outside image)
};

__device__ __forceinline__ int reflecti(int c, int n) {
    if (c < 0) c = -c;
    if (c >= n) c = 2*n - 2 - c;
    return c;
}
__device__ __forceinline__ int clampi(int c, int n) {
    return min(max(c, 0), n - 1);
}

// Gaussian 5-tap, sigma=1, normalized (matches numpy float32 kernel)
#define GW0 0.05448868454964294f
#define GW1 0.24420134723186663f
#define GW2 0.4026199364369709f

__device__ unsigned compute_edges(const float* __restrict__ img,
                                  int y0, int x0, Smem& s, int tid)
{
    const int HW = H * W;

    // Stage 1: grayscale load with reflect indexing, halo 4
    #pragma unroll
    for (int idx = tid; idx < SG*SG; idx += NTHREADS) {
        int i = idx / SG, j = idx % SG;
        int yy = reflecti(y0 - 4 + i, H);
        int xx = reflecti(x0 - 4 + j, W);
        int o = yy * W + xx;
        s.sg[i][j] = 0.299f * img[o] + 0.587f * img[o + HW] + 0.114f * img[o + 2*HW];
    }
    __syncthreads();

    // Stage 2: horizontal blur. Rows are raw (reflect-extended), columns are
    // the clamped center coordinate (emulates 'edge' pad applied to blurred).
    #pragma unroll
    for (int idx = tid; idx < SG*SB; idx += NTHREADS) {
        int i = idx / SB, j = idx % SB;
        int xc = clampi(x0 - 2 + j, W);
        int jj = xc - (x0 - 4);      // in [2, 37]
        const float* row = s.sg[i];
        s.hb[i][j] = GW0 * (row[jj-2] + row[jj+2])
                   + GW1 * (row[jj-1] + row[jj+1])
                   + GW2 *  row[jj];
    }
    __syncthreads();

    // Stage 3: vertical blur with clamped center row
    #pragma unroll
    for (int idx = tid; idx < SB*SB; idx += NTHREADS) {
        int i = idx / SB, j = idx % SB;
        int yc = clampi(y0 - 2 + i, H);
        int ii = yc - (y0 - 4);      // in [2, 37]
        s.sb[i][j] = GW0 * (s.hb[ii-2][j] + s.hb[ii+2][j])
                   + GW1 * (s.hb[ii-1][j] + s.hb[ii+1][j])
                   + GW2 *  s.hb[ii][j];
    }
    __syncthreads();

    // Stage 4: Sobel + magnitude over tile+1 halo; zero outside image (NMS zero pad)
    #pragma unroll
    for (int idx = tid; idx < SMG*SMG; idx += NTHREADS) {
        int i = idx / SMG, j = idx % SMG;
        int y = y0 - 1 + i, x = x0 - 1 + j;
        float m = 0.0f;
        if (y >= 0 && y < H && x >= 0 && x < W) {
            int bi = i + 1, bj = j + 1;   // sb index of this coordinate
            float a00 = s.sb[bi-1][bj-1], a01 = s.sb[bi-1][bj], a02 = s.sb[bi-1][bj+1];
            float a10 = s.sb[bi  ][bj-1],                       a12 = s.sb[bi  ][bj+1];
            float a20 = s.sb[bi+1][bj-1], a21 = s.sb[bi+1][bj], a22 = s.sb[bi+1][bj+1];
            float gx = (a02 + 2.0f*a12 + a22) - (a00 + 2.0f*a10 + a20);
            float gy = (a20 + 2.0f*a21 + a22) - (a00 + 2.0f*a01 + a02);
            m = sqrtf(gx*gx + gy*gy + 1e-6f);
        }
        s.sm[i][j] = m;
    }
    __syncthreads();

    // Stage 5: NMS + threshold -> 4 binary edge bits per thread
    unsigned bits = 0;
    #pragma unroll
    for (int k = 0; k < 4; k++) {
        int idx = tid + k * NTHREADS;
        int i = idx >> 5, j = idx & 31;
        int bi = i + 2, bj = j + 2;       // sb index of output coordinate
        float a00 = s.sb[bi-1][bj-1], a01 = s.sb[bi-1][bj], a02 = s.sb[bi-1][bj+1];
        float a10 = s.sb[bi  ][bj-1],                       a12 = s.sb[bi  ][bj+1];
        float a20 = s.sb[bi+1][bj-1], a21 = s.sb[bi+1][bj], a22 = s.sb[bi+1][bj+1];
        float gx = (a02 + 2.0f*a12 + a22) - (a00 + 2.0f*a10 + a20);
        float gy = (a20 + 2.0f*a21 + a22) - (a00 + 2.0f*a01 + a02);

        float ang = atan2f(gy, gx) * 57.29577951308232f;   // degrees
        int q = (int)rintf(ang * (1.0f / 45.0f));          // round-half-even, matches jnp.round
        int p = q & 7;                                      // mod 8 of value in [-4,4]
        int dr = c_dr[p], dc = c_dc[p];

        float m  = s.sm[i+1][j+1];
        float np_ = s.sm[i+1+dr][j+1+dc];
        float nn_ = s.sm[i+1-dr][j+1-dc];
        bool edge = (m > np_) & (m > nn_) & (m > 0.1f);
        bits |= ((unsigned)edge) << k;
    }
    return bits;
}

__global__ __launch_bounds__(NTHREADS)
void edge_loss_kernel(const float* __restrict__ op, const float* __restrict__ gt)
{
    __shared__ Smem s;
    __shared__ int wsum[NTHREADS / 32];

    int tid = threadIdx.x;
    int x0 = blockIdx.x * TILE;
    int y0 = blockIdx.y * TILE;
    int n  = blockIdx.z;
    size_t img_off = (size_t)n * 3 * H * W;

    unsigned ea = compute_edges(op + img_off, y0, x0, s, tid);
    __syncthreads();
    unsigned eb = compute_edges(gt + img_off, y0, x0, s, tid);

    int cnt = __popc(ea ^ eb);
    #pragma unroll
    for (int o = 16; o > 0; o >>= 1)
        cnt += __shfl_down_sync(0xffffffffu, cnt, o);
    if ((tid & 31) == 0) wsum[tid >> 5] = cnt;
    __syncthreads();
    if (tid < (NTHREADS / 32)) {
        cnt = wsum[tid];
        #pragma unroll
        for (int o = (NTHREADS / 64); o > 0; o >>= 1)
            cnt += __shfl_down_sync(0xffu, cnt, o);
        if (tid == 0) atomicAdd(&g_count, cnt);
    }
}

__global__ void zero_kernel() { g_count = 0; }

__global__ void finalize_kernel(float* out, float inv_n) {
    out[0] = (float)g_count * inv_n;
}

extern "C" void kernel_launch(void* const* d_in, const int* in_sizes, int n_in,
                              void* d_out, int out_size)
{
    const float* op = (const float*)d_in[0];
    const float* gt = (const float*)d_in[1];
    float* out = (float*)d_out;

    int batch = in_sizes[0] / (3 * H * W);   // 8
    float inv_n = 1.0f / ((float)batch * H * W);

    zero_kernel<<<1, 1>>>();
    dim3 grid(W / TILE, H / TILE, batch);
    edge_loss_kernel<<<grid, NTHREADS>>>(op, gt);
    finalize_kernel<<<1, 1>>>(out, inv_n);
}

// round 2
// speedup vs baseline: 1.3309x; 1.3309x over previous
#include <cuda_runtime.h>
#include <math.h>

#define H 1024
#define W 1024
#define TILE 64
#define SG 72   // TILE + 2*4 (gray halo)
#define SB 68   // TILE + 2*2 (blurred halo)
#define SMG 66  // TILE + 2*1 (magnitude halo)
#define NTHREADS 512

#define A_ELEMS (SG*SG)   // 5184 (>= SB*SB=4624)
#define B_ELEMS (SG*SB)   // 4896 (>= SMG*SMG=4356)

__device__ int g_count;

__device__ __forceinline__ int reflecti(int c, int n) {
    if (c < 0) c = -c;
    if (c >= n) c = 2*n - 2 - c;
    return c;
}
__device__ __forceinline__ int clampi(int c, int n) {
    return min(max(c, 0), n - 1);
}

// Gaussian 5-tap, sigma=1, normalized (matches numpy float32 kernel)
#define GW0 0.05448868454964294f
#define GW1 0.24420134723186663f
#define GW2 0.4026199364369709f

// tan(22.5 deg), tan(67.5 deg)
#define T_LO 0.41421356237309503f
#define T_HI 2.414213562373095f

__device__ unsigned compute_edges(const float* __restrict__ img,
                                  int y0, int x0,
                                  float* A, float* B, unsigned char* axc,
                                  int tid)
{
    const int HW = H * W;

    // Stage 1: grayscale with reflect indexing, halo 4  ->  A as [SG][SG]
    for (int idx = tid; idx < SG*SG; idx += NTHREADS) {
        int i = idx / SG, j = idx % SG;
        int yy = reflecti(y0 - 4 + i, H);
        int xx = reflecti(x0 - 4 + j, W);
        int o = yy * W + xx;
        A[idx] = 0.299f * img[o] + 0.587f * img[o + HW] + 0.114f * img[o + 2*HW];
    }
    __syncthreads();

    // Stage 2: horizontal blur, clamped center column ('edge' pad) -> B as [SG][SB]
    for (int idx = tid; idx < SG*SB; idx += NTHREADS) {
        int i = idx / SB, j = idx % SB;
        int xc = clampi(x0 - 2 + j, W);
        int jj = xc - (x0 - 4);                // in [2, SG-3]
        const float* row = A + i * SG;
        B[idx] = GW0 * (row[jj-2] + row[jj+2])
               + GW1 * (row[jj-1] + row[jj+1])
               + GW2 *  row[jj];
    }
    __syncthreads();

    // Stage 3: vertical blur, clamped center row -> A as [SB][SB]
    for (int idx = tid; idx < SB*SB; idx += NTHREADS) {
        int i = idx / SB, j = idx % SB;
        int yc = clampi(y0 - 2 + i, H);
        int ii = yc - (y0 - 4);                // in [2, SG-3]
        A[idx] = GW0 * (B[(ii-2)*SB + j] + B[(ii+2)*SB + j])
               + GW1 * (B[(ii-1)*SB + j] + B[(ii+1)*SB + j])
               + GW2 *  B[ii*SB + j];
    }
    __syncthreads();

    // Stage 4: Sobel -> squared magnitude (0 outside image) -> B as [SMG][SMG],
    //          plus 2-bit axis code for interior pixels -> axc[TILE*TILE]
    for (int idx = tid; idx < SMG*SMG; idx += NTHREADS) {
        int i = idx / SMG, j = idx % SMG;
        int y = y0 - 1 + i, x = x0 - 1 + j;
        float msq = 0.0f;
        float gx = 0.0f, gy = 0.0f;
        if (y >= 0 && y < H && x >= 0 && x < W) {
            const float* c = A + (i+1)*SB + (j+1);
            float a00 = c[-SB-1], a01 = c[-SB], a02 = c[-SB+1];
            float a10 = c[-1],                  a12 = c[+1];
            float a20 = c[ SB-1], a21 = c[ SB], a22 = c[ SB+1];
            gx = (a02 + 2.0f*a12 + a22) - (a00 + 2.0f*a10 + a20);
            gy = (a20 + 2.0f*a21 + a22) - (a00 + 2.0f*a01 + a02);
            msq = fmaf(gx, gx, gy*gy);
        }
        B[idx] = msq;
        if (i >= 1 && i <= TILE && j >= 1 && j <= TILE) {
            float ax = fabsf(gx), ay = fabsf(gy);
            unsigned char code;
            if (ay <= T_LO * ax)      code = 0;                       // horizontal axis
            else if (ay >= T_HI * ax) code = 1;                       // vertical axis
            else code = ((gx > 0.0f) == (gy > 0.0f)) ? 2 : 3;         // diagonals
            axc[(i-1)*TILE + (j-1)] = code;
        }
    }
    __syncthreads();

    // Stage 5: NMS + threshold -> 8 edge bits per thread
    unsigned bits = 0;
    #pragma unroll
    for (int k = 0; k < 8; k++) {
        int idx = tid + k * NTHREADS;
        int i = idx >> 6, j = idx & 63;
        int ci = (i+1)*SMG + (j+1);
        float c = B[ci];
        int code = axc[idx];
        int off = (code == 0) ? 1 : (code == 1) ? SMG : (code == 2) ? (SMG-1) : (SMG+1);
        bool edge = (c > B[ci + off]) & (c > B[ci - off]) & (c > 0.009999f);
        bits |= ((unsigned)edge) << k;
    }
    return bits;
}

__global__ __launch_bounds__(NTHREADS)
void edge_loss_kernel(const float* __restrict__ op, const float* __restrict__ gt)
{
    __shared__ float bufA[A_ELEMS];
    __shared__ float bufB[B_ELEMS];
    __shared__ unsigned char axc[TILE*TILE];
    __shared__ int wsum[NTHREADS / 32];

    int tid = threadIdx.x;
    int x0 = blockIdx.x * TILE;
    int y0 = blockIdx.y * TILE;
    size_t img_off = (size_t)blockIdx.z * 3 * H * W;

    unsigned ea = compute_edges(op + img_off, y0, x0, bufA, bufB, axc, tid);
    __syncthreads();
    unsigned eb = compute_edges(gt + img_off, y0, x0, bufA, bufB, axc, tid);

    int cnt = __popc(ea ^ eb);
    #pragma unroll
    for (int o = 16; o > 0; o >>= 1)
        cnt += __shfl_down_sync(0xffffffffu, cnt, o);
    if ((tid & 31) == 0) wsum[tid >> 5] = cnt;
    __syncthreads();
    if (tid < (NTHREADS / 32)) {
        cnt = wsum[tid];
        #pragma unroll
        for (int o = (NTHREADS / 64); o > 0; o >>= 1)
            cnt += __shfl_down_sync(0xffffu, cnt, o);
        if (tid == 0) atomicAdd(&g_count, cnt);
    }
}

__global__ void zero_kernel() { g_count = 0; }

__global__ void finalize_kernel(float* out, float inv_n) {
    out[0] = (float)g_count * inv_n;
}

extern "C" void kernel_launch(void* const* d_in, const int* in_sizes, int n_in,
                              void* d_out, int out_size)
{
    const float* op = (const float*)d_in[0];
    const float* gt = (const float*)d_in[1];
    float* out = (float*)d_out;

    int batch = in_sizes[0] / (3 * H * W);   // 8
    float inv_n = 1.0f / ((float)batch * H * W);

    zero_kernel<<<1, 1>>>();
    dim3 grid(W / TILE, H / TILE, batch);
    edge_loss_kernel<<<grid, NTHREADS>>>(op, gt);
    finalize_kernel<<<1, 1>>>(out, inv_n);
}

// round 3
// speedup vs baseline: 1.7371x; 1.3052x over previous
#include <cuda_runtime.h>
#include <math.h>

#define H 1024
#define W 1024
#define HW (H*W)
#define TX 64
#define TY 32
#define SGX 72   // TX + 8
#define SGY 40   // TY + 8
#define SBX 68   // TX + 4
#define SBY 36   // TY + 4
#define SMX 66   // TX + 2
#define SMY 34   // TY + 2
#define NT 512

typedef unsigned long long u64;

__device__ int g_count = 0;
__device__ int g_ticket = 0;

// ---- packed f32x2 helpers (Blackwell FFMA2 path) ----
__device__ __forceinline__ u64 pk(float lo, float hi) {
    u64 r; asm("mov.b64 %0,{%1,%2};" : "=l"(r) : "f"(lo), "f"(hi)); return r;
}
__device__ __forceinline__ void upk(u64 v, float& lo, float& hi) {
    asm("mov.b64 {%0,%1},%2;" : "=f"(lo), "=f"(hi) : "l"(v));
}
__device__ __forceinline__ u64 fadd2(u64 a, u64 b) {
    u64 r; asm("add.rn.f32x2 %0,%1,%2;" : "=l"(r) : "l"(a), "l"(b)); return r;
}
__device__ __forceinline__ u64 fmul2(u64 a, u64 b) {
    u64 r; asm("mul.rn.f32x2 %0,%1,%2;" : "=l"(r) : "l"(a), "l"(b)); return r;
}
__device__ __forceinline__ u64 ffma2(u64 a, u64 b, u64 c) {
    u64 r; asm("fma.rn.f32x2 %0,%1,%2,%3;" : "=l"(r) : "l"(a), "l"(b), "l"(c)); return r;
}
__device__ __forceinline__ u64 fneg2(u64 a) { return a ^ 0x8000000080000000ULL; }
__device__ __forceinline__ u64 fsub2(u64 a, u64 b) { return fadd2(a, fneg2(b)); }

__device__ __forceinline__ int reflecti(int c, int n) {
    if (c < 0) c = -c;
    if (c >= n) c = 2*n - 2 - c;
    return c;
}
__device__ __forceinline__ int clampi(int c, int n) {
    return min(max(c, 0), n - 1);
}

#define GW0 0.05448868454964294f
#define GW1 0.24420134723186663f
#define GW2 0.4026199364369709f
#define T_LO 0.41421356237309503f
#define T_HI 2.414213562373095f
#define TH2  0.009999f

// NMS neighbor offset in the [SMY][SMX] squared-magnitude grid
__device__ __forceinline__ int axis_off(float gx, float gy) {
    float ax = fabsf(gx), ay = fabsf(gy);
    if (ay <= T_LO * ax) return 1;            // horizontal axis
    if (ay >= T_HI * ax) return SMX;          // vertical axis
    return ((__float_as_int(gx) ^ __float_as_int(gy)) >= 0) ? (SMX - 1) : (SMX + 1);
}

__global__ __launch_bounds__(NT)
void edge_loss_kernel(const float* __restrict__ op, const float* __restrict__ gt,
                      float* __restrict__ out, float inv_n)
{
    __shared__ u64   sA[SGY * SGX];   // gray pairs -> later vblur pairs [SBY][SBX]
    __shared__ u64   sB[SGY * SBX];   // hblur pairs -> later msq pairs [SMY][SMX]
    __shared__ short snoff[TY * TX];  // packed int8 NMS offsets (op | gt<<8)
    __shared__ int   wsum[NT / 32];

    const int tid = threadIdx.x;
    const int x0 = blockIdx.x * TX;
    const int y0 = blockIdx.y * TY;
    const size_t ib = (size_t)blockIdx.z * 3 * HW;
    const float* __restrict__ opi = op + ib;
    const float* __restrict__ gti = gt + ib;

    // ---- Stage 1: grayscale pairs (reflect halo 4) -> sA[SGY][SGX] ----
    if (x0 != 0 && x0 != W - TX) {
        // fast path: x window [x0-4, x0+68) fully interior & 16B aligned
        #pragma unroll 1
        for (int g = tid; g < SGY * 18; g += NT) {
            int i = g / 18, q = g - i * 18;
            int yy = reflecti(y0 - 4 + i, H);
            const float* po = opi + yy * W + (x0 - 4) + q * 4;
            const float* pg = gti + yy * W + (x0 - 4) + q * 4;
            float4 ro = *(const float4*)(po);
            float4 go = *(const float4*)(po + HW);
            float4 bo = *(const float4*)(po + 2 * HW);
            float4 rg = *(const float4*)(pg);
            float4 gg = *(const float4*)(pg + HW);
            float4 bg = *(const float4*)(pg + 2 * HW);
            float o0 = fmaf(0.299f, ro.x, fmaf(0.587f, go.x, 0.114f * bo.x));
            float o1 = fmaf(0.299f, ro.y, fmaf(0.587f, go.y, 0.114f * bo.y));
            float o2 = fmaf(0.299f, ro.z, fmaf(0.587f, go.z, 0.114f * bo.z));
            float o3 = fmaf(0.299f, ro.w, fmaf(0.587f, go.w, 0.114f * bo.w));
            float t0 = fmaf(0.299f, rg.x, fmaf(0.587f, gg.x, 0.114f * bg.x));
            float t1 = fmaf(0.299f, rg.y, fmaf(0.587f, gg.y, 0.114f * bg.y));
            float t2 = fmaf(0.299f, rg.z, fmaf(0.587f, gg.z, 0.114f * bg.z));
            float t3 = fmaf(0.299f, rg.w, fmaf(0.587f, gg.w, 0.114f * bg.w));
            u64* dst = &sA[i * SGX + q * 4];
            *(longlong2*)(dst)     = make_longlong2((long long)pk(o0, t0), (long long)pk(o1, t1));
            *(longlong2*)(dst + 2) = make_longlong2((long long)pk(o2, t2), (long long)pk(o3, t3));
        }
    } else {
        #pragma unroll 1
        for (int e = tid; e < SGY * SGX; e += NT) {
            int i = e / SGX, j = e - i * SGX;
            int yy = reflecti(y0 - 4 + i, H);
            int xx = reflecti(x0 - 4 + j, W);
            int o = yy * W + xx;
            float a = fmaf(0.299f, opi[o], fmaf(0.587f, opi[o + HW], 0.114f * opi[o + 2*HW]));
            float b = fmaf(0.299f, gti[o], fmaf(0.587f, gti[o + HW], 0.114f * gti[o + 2*HW]));
            sA[e] = pk(a, b);
        }
    }
    __syncthreads();

    const u64 K0 = pk(GW0, GW0), K1 = pk(GW1, GW1), K2 = pk(GW2, GW2);

    // ---- Stage 2: horizontal blur (edge-clamped center col) -> sB[SGY][SBX] ----
    #pragma unroll 1
    for (int e = tid; e < SGY * SBX; e += NT) {
        int i = e / SBX, j = e - i * SBX;
        int jj = clampi(x0 - 2 + j, W) - (x0 - 4);
        const u64* row = &sA[i * SGX + jj];
        u64 acc = fmul2(fadd2(row[-2], row[2]), K0);
        acc = ffma2(fadd2(row[-1], row[1]), K1, acc);
        acc = ffma2(row[0], K2, acc);
        sB[e] = acc;
    }
    __syncthreads();

    // ---- Stage 3: vertical blur (edge-clamped center row) -> sA overlay [SBY][SBX] ----
    #pragma unroll 1
    for (int e = tid; e < SBY * SBX; e += NT) {
        int i = e / SBX, j = e - i * SBX;
        int ii = clampi(y0 - 2 + i, H) - (y0 - 4);
        const u64* col = &sB[ii * SBX + j];
        u64 acc = fmul2(fadd2(col[-2*SBX], col[2*SBX]), K0);
        acc = ffma2(fadd2(col[-SBX], col[SBX]), K1, acc);
        acc = ffma2(col[0], K2, acc);
        sA[i * SBX + j] = acc;
    }
    __syncthreads();

    // ---- Stage 4: Sobel -> squared magnitude pairs in sB overlay [SMY][SMX] + NMS offsets ----
    const u64 TWO = pk(2.0f, 2.0f);
    #pragma unroll 1
    for (int e = tid; e < SMY * SMX; e += NT) {
        int i = e / SMX, j = e - i * SMX;
        int y = y0 - 1 + i, x = x0 - 1 + j;
        if ((unsigned)y < H && (unsigned)x < W) {
            const u64* c = &sA[(i + 1) * SBX + (j + 1)];
            u64 a00 = c[-SBX-1], a01 = c[-SBX], a02 = c[-SBX+1];
            u64 a10 = c[-1],                    a12 = c[1];
            u64 a20 = c[ SBX-1], a21 = c[ SBX], a22 = c[ SBX+1];
            u64 s0 = fsub2(a02, a00), s1 = fsub2(a12, a10), s2 = fsub2(a22, a20);
            u64 gx = ffma2(s1, TWO, fadd2(s0, s2));
            u64 u0 = fsub2(a20, a00), u1 = fsub2(a21, a01), u2 = fsub2(a22, a02);
            u64 gy = ffma2(u1, TWO, fadd2(u0, u2));
            sB[e] = ffma2(gx, gx, fmul2(gy, gy));
            if (i >= 1 && i <= TY && j >= 1 && j <= TX) {
                float gxo, gxg, gyo, gyg;
                upk(gx, gxo, gxg);
                upk(gy, gyo, gyg);
                int oo = axis_off(gxo, gyo);
                int og = axis_off(gxg, gyg);
                snoff[(i - 1) * TX + (j - 1)] = (short)(oo | (og << 8));
            }
        } else {
            sB[e] = 0ULL;
        }
    }
    __syncthreads();

    // ---- Stage 5: NMS + threshold + XOR count ----
    int cnt = 0;
    const float* Bf = (const float*)sB;
    #pragma unroll
    for (int k = 0; k < 4; k++) {
        int px = tid + k * NT;
        int i = px >> 6, j = px & 63;
        int ci = (i + 1) * SMX + (j + 1);
        float co, cg;
        upk(sB[ci], co, cg);
        int s = snoff[px];
        int oo = s & 0xff;
        int og = (s >> 8) & 0xff;
        bool eo = (co > Bf[2*(ci + oo)])     & (co > Bf[2*(ci - oo)])     & (co > TH2);
        bool eg = (cg > Bf[2*(ci + og) + 1]) & (cg > Bf[2*(ci - og) + 1]) & (cg > TH2);
        cnt += (int)(eo != eg);
    }

    // ---- block reduce + fused finalize ----
    #pragma unroll
    for (int o = 16; o > 0; o >>= 1)
        cnt += __shfl_down_sync(0xffffffffu, cnt, o);
    if ((tid & 31) == 0) wsum[tid >> 5] = cnt;
    __syncthreads();
    if (tid < (NT / 32)) {
        cnt = wsum[tid];
        #pragma unroll
        for (int o = (NT / 64); o > 0; o >>= 1)
            cnt += __shfl_down_sync(0xffffu, cnt, o);
        if (tid == 0) {
            atomicAdd(&g_count, cnt);
            __threadfence();
            int nb = gridDim.x * gridDim.y * gridDim.z;
            int t = atomicAdd(&g_ticket, 1);
            if (t == nb - 1) {
                out[0] = (float)atomicAdd(&g_count, 0) * inv_n;
                g_count = 0;
                g_ticket = 0;
            }
        }
    }
}

extern "C" void kernel_launch(void* const* d_in, const int* in_sizes, int n_in,
                              void* d_out, int out_size)
{
    const float* op = (const float*)d_in[0];
    const float* gt = (const float*)d_in[1];
    float* out = (float*)d_out;

    int batch = in_sizes[0] / (3 * HW);
    float inv_n = 1.0f / ((float)batch * HW);

    dim3 grid(W / TX, H / TY, batch);
    edge_loss_kernel<<<grid, NT>>>(op, gt, out, inv_n);
}